// round 13
// baseline (speedup 1.0000x reference)
#include <cuda_runtime.h>
#include <cuda_bf16.h>
#include <math.h>

// ---------------- problem constants ----------------
#define BB 32
#define LL 2048
#define CC 32
#define PLEN 16
#define PP 128
#define DD 64
#define HENC 256
#define HDEC 256
#define KK 512
#define NHEAD 4
#define DH 16
#define NSEQ 1024
#define NTOK (NSEQ*PP)

#define O_ZQ   ((size_t)2)
#define O_R    ((size_t)(2 + (size_t)NTOK*DD))
#define O_IDX  ((size_t)(O_R + (size_t)BB*LL*CC))
#define O_PERP ((size_t)(O_IDX + (size_t)NTOK))

// ---------------- device scratch ----------------
__device__ float g_mean[NSEQ];
__device__ float g_istd[NSEQ];
__device__ float g_stdv[NSEQ];
__device__ float g_z [(size_t)NTOK*DD];
__device__ float g_zq[(size_t)NTOK*DD];
__device__ float g_counts[KK];
__device__ float g_csum;
__device__ float g_rsum;

// ---------------- init ----------------
__global__ void k_init() {
    int t = threadIdx.x;
    if (t < KK) g_counts[t] = 0.f;
    if (t == 0) { g_csum = 0.f; g_rsum = 0.f; }
}

// ---------------- RevIN stats ----------------
__global__ void k_revin(const float* __restrict__ x) {
    __shared__ float ps[32][33], pq[32][33];
    int b = blockIdx.x;
    int c = threadIdx.x & 31, ls = threadIdx.x >> 5;
    const float* xb = x + (size_t)b * LL * CC;
    float s = 0.f, q = 0.f;
    for (int l = ls; l < LL; l += 32) {
        float v = xb[(size_t)l * CC + c];
        s += v; q += v * v;
    }
    ps[ls][c] = s; pq[ls][c] = q;
    __syncthreads();
    if (threadIdx.x < 32) {
        int cc = threadIdx.x;
        float S = 0.f, Q = 0.f;
        for (int i = 0; i < 32; i++) { S += ps[i][cc]; Q += pq[i][cc]; }
        float m = S / (float)LL;
        float var = Q / (float)LL - m * m;
        float sd = sqrtf(var + 1e-5f);
        g_mean[b * 32 + cc] = m;
        g_stdv[b * 32 + cc] = sd;
        g_istd[b * 32 + cc] = 1.f / sd;
    }
}

// ---------------- fused encoder (512 threads) ----------------
// smem identical layout to R6 version; per-thread tiles halved.
#define ENC_SMEM 206336
#define ETH 512
__global__ __launch_bounds__(ETH, 1) void k_encoder(
    const float* __restrict__ x,
    const float* __restrict__ revin_w, const float* __restrict__ revin_b,
    const float* __restrict__ inp_W, const float* __restrict__ inp_b,
    const float* __restrict__ Wq, const float* __restrict__ bq,
    const float* __restrict__ Wk, const float* __restrict__ bk,
    const float* __restrict__ Wv, const float* __restrict__ bv,
    const float* __restrict__ Wo, const float* __restrict__ bo,
    const float* __restrict__ ln1_g, const float* __restrict__ ln1_b,
    const float* __restrict__ fW1, const float* __restrict__ fb1,
    const float* __restrict__ fW2, const float* __restrict__ fb2,
    const float* __restrict__ ln2_g, const float* __restrict__ ln2_b)
{
    extern __shared__ float S[];
    float* h  = S;
    float* A  = S + 8320;
    float* Bb = S + 16640;
    float* Cc = S + 24960;
    float* wb = S + 33280;
    const int tid = threadIdx.x;
    const int n = blockIdx.x;
    const int b = n >> 5, c = n & 31;
    const float mu = g_mean[n], is = g_istd[n];
    const float rw = revin_w[c], rb = revin_b[c];
    const float* xb = x + (size_t)b * LL * CC + c;

    // P0
    for (int i = tid; i < 2048; i += ETH)
        A[i] = (xb[(size_t)i * CC] - mu) * is * rw + rb;
    for (int i = tid; i < 1024 + 64; i += ETH)
        wb[i] = (i < 1024) ? inp_W[i] : inp_b[i - 1024];
    __syncthreads();

    // P1: h = xn @ inp_W + b
    for (int i = tid; i < 8192; i += ETH) {
        int p = i >> 6, d = i & 63;
        float acc = wb[1024 + d];
        const float* xn = A + p * 16;
        #pragma unroll
        for (int j = 0; j < 16; j++) acc = __fmaf_rn(xn[j], wb[j * 64 + d], acc);
        h[p * 65 + d] = acc;
    }

    // P2: q,k,v projections — 4tok x 4d register tiles
    {
        const float* Ws[3] = {Wq, Wk, Wv};
        const float* bs[3] = {bq, bk, bv};
        float* dsts[3] = {A, Bb, Cc};
        const int tg4 = tid >> 4;          // 0..31 -> 4 tokens each
        const int dq4 = (tid & 15) * 4;    // 4 d's
        for (int m = 0; m < 3; m++) {
            __syncthreads();
            const float* W = Ws[m]; const float* bi = bs[m];
            for (int i = tid; i < 4160; i += ETH)
                wb[i] = (i < 4096) ? W[i] : bi[i - 4096];
            __syncthreads();
            float acc[4][4];
            {
                float4 b4 = *(const float4*)&wb[4096 + dq4];
                #pragma unroll
                for (int j = 0; j < 4; j++) {
                    acc[j][0] = b4.x; acc[j][1] = b4.y; acc[j][2] = b4.z; acc[j][3] = b4.w;
                }
            }
            for (int e = 0; e < 64; e++) {
                float4 w4 = *(const float4*)&wb[e * 64 + dq4];
                #pragma unroll
                for (int j = 0; j < 4; j++) {
                    float hv = h[(tg4 * 4 + j) * 65 + e];
                    acc[j][0] = __fmaf_rn(hv, w4.x, acc[j][0]);
                    acc[j][1] = __fmaf_rn(hv, w4.y, acc[j][1]);
                    acc[j][2] = __fmaf_rn(hv, w4.z, acc[j][2]);
                    acc[j][3] = __fmaf_rn(hv, w4.w, acc[j][3]);
                }
            }
            float* dst = dsts[m];
            #pragma unroll
            for (int j = 0; j < 4; j++) {
                int row = (tg4 * 4 + j) * 65 + dq4;
                dst[row + 0] = acc[j][0]; dst[row + 1] = acc[j][1];
                dst[row + 2] = acc[j][2]; dst[row + 3] = acc[j][3];
            }
        }
    }
    __syncthreads();

    // P3: attention — 512 (head,query) rows, 1 per thread, online softmax.
    {
        int row = tid;
        int hh = row >> 7, qq = row & 127;
        int off = hh * 16;
        float qv[16], acc[16];
        #pragma unroll
        for (int t = 0; t < 16; t++) { qv[t] = A[qq * 65 + off + t]; acc[t] = 0.f; }
        float mx = -1e30f, l = 0.f;
        for (int j = 0; j < 128; j++) {
            const float* kj = Bb + j * 65 + off;
            float s = 0.f;
            #pragma unroll
            for (int t = 0; t < 16; t++) s += qv[t] * kj[t];
            s *= 0.25f;
            float nm = fmaxf(mx, s);
            float corr = __expf(mx - nm);
            float pw = __expf(s - nm);
            l = l * corr + pw;
            const float* vj = Cc + j * 65 + off;
            #pragma unroll
            for (int t = 0; t < 16; t++) acc[t] = acc[t] * corr + pw * vj[t];
            mx = nm;
        }
        float il = 1.f / l;
        #pragma unroll
        for (int t = 0; t < 16; t++) A[qq * 65 + off + t] = acc[t] * il;
    }
    __syncthreads();

    // P4: o = a @ Wo + bo + h -> Bb; then LN1 -> h
    for (int i = tid; i < 4160; i += ETH)
        wb[i] = (i < 4096) ? Wo[i] : bo[i - 4096];
    __syncthreads();
    {
        const int tg4 = tid >> 4;
        const int dq4 = (tid & 15) * 4;
        float acc[4][4];
        {
            float4 b4 = *(const float4*)&wb[4096 + dq4];
            #pragma unroll
            for (int j = 0; j < 4; j++) {
                int row = (tg4 * 4 + j) * 65 + dq4;
                acc[j][0] = b4.x + h[row + 0];
                acc[j][1] = b4.y + h[row + 1];
                acc[j][2] = b4.z + h[row + 2];
                acc[j][3] = b4.w + h[row + 3];
            }
        }
        for (int e = 0; e < 64; e++) {
            float4 w4 = *(const float4*)&wb[e * 64 + dq4];
            #pragma unroll
            for (int j = 0; j < 4; j++) {
                float av = A[(tg4 * 4 + j) * 65 + e];
                acc[j][0] = __fmaf_rn(av, w4.x, acc[j][0]);
                acc[j][1] = __fmaf_rn(av, w4.y, acc[j][1]);
                acc[j][2] = __fmaf_rn(av, w4.z, acc[j][2]);
                acc[j][3] = __fmaf_rn(av, w4.w, acc[j][3]);
            }
        }
        #pragma unroll
        for (int j = 0; j < 4; j++) {
            int row = (tg4 * 4 + j) * 65 + dq4;
            Bb[row + 0] = acc[j][0]; Bb[row + 1] = acc[j][1];
            Bb[row + 2] = acc[j][2]; Bb[row + 3] = acc[j][3];
        }
    }
    __syncthreads();
    // LN1: warp per token (16 warps)
    {
        int w = tid >> 5, lane = tid & 31;
        for (int p = w; p < 128; p += 16) {
            float v0 = Bb[p * 65 + lane], v1 = Bb[p * 65 + lane + 32];
            float s = v0 + v1;
            #pragma unroll
            for (int o = 16; o > 0; o >>= 1) s += __shfl_xor_sync(~0u, s, o);
            float mean = s * (1.f / 64.f);
            float d0 = v0 - mean, d1 = v1 - mean;
            float q = d0 * d0 + d1 * d1;
            #pragma unroll
            for (int o = 16; o > 0; o >>= 1) q += __shfl_xor_sync(~0u, q, o);
            float r = rsqrtf(q * (1.f / 64.f) + 1e-5f);
            h[p * 65 + lane]      = d0 * r * ln1_g[lane]      + ln1_b[lane];
            h[p * 65 + lane + 32] = d1 * r * ln1_g[lane + 32] + ln1_b[lane + 32];
        }
    }
    __syncthreads();

    // P5: FFN in four 32-token quarters; W1,W2 staged once.
    float* WB1 = S + 8320;
    float* WB2 = S + 24704;
    float* U   = S + 41088;   // 32 x 260
    float* Yq  = S + 49408;   // 32 x 68
    for (int i = tid; i < 16384; i += ETH) WB1[i] = fW1[i];
    for (int i = tid; i < 16384; i += ETH) WB2[i] = fW2[i];
    __syncthreads();
    const int tgf = tid >> 6;            // 0..7 -> 4 tokens each
    const int hq4 = (tid & 63) * 4;      // 4 of 256 hidden
    const int tg1 = tid >> 4;            // 0..31 -> 1 token
    const int dq4 = (tid & 15) * 4;      // 4 of 64 d
    for (int qtr = 0; qtr < 4; qtr++) {
        int tb = qtr * 32;
        // FFN1: u = relu(h @ W1 + b1), 4tok x 4h tiles
        {
            float acc[4][4];
            float4 b4 = *(const float4*)&fb1[hq4];
            #pragma unroll
            for (int j = 0; j < 4; j++) {
                acc[j][0] = b4.x; acc[j][1] = b4.y; acc[j][2] = b4.z; acc[j][3] = b4.w;
            }
            for (int e = 0; e < 64; e++) {
                float4 w4 = *(const float4*)&WB1[e * 256 + hq4];
                #pragma unroll
                for (int j = 0; j < 4; j++) {
                    float hv = h[(tb + tgf * 4 + j) * 65 + e];
                    acc[j][0] = __fmaf_rn(hv, w4.x, acc[j][0]);
                    acc[j][1] = __fmaf_rn(hv, w4.y, acc[j][1]);
                    acc[j][2] = __fmaf_rn(hv, w4.z, acc[j][2]);
                    acc[j][3] = __fmaf_rn(hv, w4.w, acc[j][3]);
                }
            }
            #pragma unroll
            for (int j = 0; j < 4; j++) {
                float4 o4;
                o4.x = fmaxf(acc[j][0], 0.f); o4.y = fmaxf(acc[j][1], 0.f);
                o4.z = fmaxf(acc[j][2], 0.f); o4.w = fmaxf(acc[j][3], 0.f);
                *(float4*)&U[(tgf * 4 + j) * 260 + hq4] = o4;
            }
        }
        __syncthreads();
        // FFN2: o = u @ W2 + b2 + h, 1tok x 4d tiles -> Yq
        {
            float acc[4];
            int tok = tb + tg1;
            acc[0] = fb2[dq4 + 0] + h[tok * 65 + dq4 + 0];
            acc[1] = fb2[dq4 + 1] + h[tok * 65 + dq4 + 1];
            acc[2] = fb2[dq4 + 2] + h[tok * 65 + dq4 + 2];
            acc[3] = fb2[dq4 + 3] + h[tok * 65 + dq4 + 3];
            for (int e2 = 0; e2 < 256; e2++) {
                float4 w4 = *(const float4*)&WB2[e2 * 64 + dq4];
                float uv = U[tg1 * 260 + e2];
                acc[0] = __fmaf_rn(uv, w4.x, acc[0]);
                acc[1] = __fmaf_rn(uv, w4.y, acc[1]);
                acc[2] = __fmaf_rn(uv, w4.z, acc[2]);
                acc[3] = __fmaf_rn(uv, w4.w, acc[3]);
            }
            float4 o4; o4.x = acc[0]; o4.y = acc[1]; o4.z = acc[2]; o4.w = acc[3];
            *(float4*)&Yq[tg1 * 68 + dq4] = o4;
        }
        __syncthreads();
        // LN2 for this quarter -> h (16 warps, 32 tokens)
        {
            int w = tid >> 5, lane = tid & 31;
            for (int tl = w; tl < 32; tl += 16) {
                float v0 = Yq[tl * 68 + lane], v1 = Yq[tl * 68 + lane + 32];
                float s = v0 + v1;
                #pragma unroll
                for (int o = 16; o > 0; o >>= 1) s += __shfl_xor_sync(~0u, s, o);
                float mean = s * (1.f / 64.f);
                float d0 = v0 - mean, d1 = v1 - mean;
                float q = d0 * d0 + d1 * d1;
                #pragma unroll
                for (int o = 16; o > 0; o >>= 1) q += __shfl_xor_sync(~0u, q, o);
                float r = rsqrtf(q * (1.f / 64.f) + 1e-5f);
                h[(tb + tl) * 65 + lane]      = d0 * r * ln2_g[lane]      + ln2_b[lane];
                h[(tb + tl) * 65 + lane + 32] = d1 * r * ln2_g[lane + 32] + ln2_b[lane + 32];
            }
        }
        __syncthreads();
    }
    // write z (packed)
    float* zo = g_z + (size_t)n * 8192;
    for (int i = tid; i < 8192; i += ETH) zo[i] = h[(i >> 6) * 65 + (i & 63)];
}

// ---------------- quantizer (512 threads, 2tok x 8code tiles) ----------------
// dist chain identical to reference: fl(fl(z2+e2) - fl(2*dot)), e-loop sequential.
#define QUANT_SMEM ((8448+8448+128+128+1024+1024)*4)
#define QTH 512
__global__ __launch_bounds__(QTH, 1) void k_quant(
    const float* __restrict__ cb, float* __restrict__ out, int out_size)
{
    extern __shared__ float S[];
    float* zT   = S;
    float* cbsT = S + 8448;
    float* e2s  = S + 16896;
    float* z2s  = S + 17024;
    float* bd   = S + 17152;
    int*   bki  = (int*)(S + 18176);
    __shared__ float red[16];

    int n = blockIdx.x, tid = threadIdx.x;
    const float* z = g_z + (size_t)n * 8192;
    for (int i = tid; i < 8192; i += QTH) {
        int tok = i >> 6, e = i & 63;
        zT[e * 132 + tok] = z[i];
    }
    __syncthreads();
    if (tid < 128) {
        float acc = 0.f;
        #pragma unroll 8
        for (int e = 0; e < 64; e++) {
            float v = zT[e * 132 + tid];
            acc = __fmaf_rn(v, v, acc);
        }
        z2s[tid] = acc;
    }

    const int tok0 = (tid & 63) * 2;   // 2 tokens
    const int crow = tid >> 6;         // 0..7: 8 codes per sub
    float bestd[2]; int bestk[2];
    #pragma unroll
    for (int t = 0; t < 2; t++) { bestd[t] = 1e30f; bestk[t] = 0; }

    for (int ch = 0; ch < 4; ch++) {
        __syncthreads();
        for (int i = tid; i < 8192; i += QTH) {
            int cl = i >> 6, e = i & 63;
            cbsT[e * 132 + cl] = cb[ch * 8192 + i];
        }
        __syncthreads();
        if (tid < 128) {
            float s = 0.f;
            #pragma unroll 8
            for (int e = 0; e < 64; e++) {
                float v = cbsT[e * 132 + tid];
                s = __fmaf_rn(v, v, s);
            }
            e2s[tid] = s;
        }
        __syncthreads();
        #pragma unroll
        for (int sub = 0; sub < 2; sub++) {
            int cbase = sub * 64 + crow * 8;
            float acc[2][8];
            #pragma unroll
            for (int t = 0; t < 2; t++)
                #pragma unroll
                for (int cc2 = 0; cc2 < 8; cc2++) acc[t][cc2] = 0.f;
            for (int e = 0; e < 64; e++) {
                float2 zv = *(const float2*)&zT[e * 132 + tok0];
                float4 c0 = *(const float4*)&cbsT[e * 132 + cbase];
                float4 c1 = *(const float4*)&cbsT[e * 132 + cbase + 4];
                float cvals[8] = {c0.x, c0.y, c0.z, c0.w, c1.x, c1.y, c1.z, c1.w};
                float zvals[2] = {zv.x, zv.y};
                #pragma unroll
                for (int t = 0; t < 2; t++)
                    #pragma unroll
                    for (int cc2 = 0; cc2 < 8; cc2++)
                        acc[t][cc2] = __fmaf_rn(cvals[cc2], zvals[t], acc[t][cc2]);
            }
            #pragma unroll
            for (int cc2 = 0; cc2 < 8; cc2++) {
                int kl = cbase + cc2;
                int kg = ch * 128 + kl;
                float e2v = e2s[kl];
                #pragma unroll
                for (int t = 0; t < 2; t++) {
                    float dist = __fsub_rn(__fadd_rn(z2s[tok0 + t], e2v),
                                           __fmul_rn(2.0f, acc[t][cc2]));
                    if (dist < bestd[t]) { bestd[t] = dist; bestk[t] = kg; }
                }
            }
        }
    }
    #pragma unroll
    for (int t = 0; t < 2; t++) {
        bd[crow * 128 + tok0 + t] = bestd[t];
        bki[crow * 128 + tok0 + t] = bestk[t];
    }
    __syncthreads();
    if (tid < 128) {
        float d0 = bd[tid]; int k0 = bki[tid];
        #pragma unroll
        for (int r = 1; r < 8; r++) {
            float d1 = bd[r * 128 + tid]; int k1 = bki[r * 128 + tid];
            if (d1 < d0 || (d1 == d0 && k1 < k0)) { d0 = d1; k0 = k1; }
        }
        bki[tid] = k0;
        atomicAdd(&g_counts[k0], 1.f);
        size_t oi = O_IDX + (size_t)n * 128 + tid;
        if (oi < (size_t)out_size) out[oi] = (float)k0;
    }
    __syncthreads();
    float csum = 0.f;
    float* zq = g_zq + (size_t)n * 8192;
    for (int i = tid; i < 8192; i += QTH) {
        int t2 = i >> 6, e = i & 63;
        int kf = bki[t2];
        float q = cb[kf * 64 + e];
        float zz = z[i];
        float d = __fsub_rn(q, zz);
        csum += d * d;
        float q_st = __fadd_rn(zz, d);
        zq[i] = q_st;
        size_t oo = O_ZQ + (size_t)n * 8192 + i;
        if (oo < (size_t)out_size) out[oo] = q_st;
    }
    #pragma unroll
    for (int o = 16; o > 0; o >>= 1) csum += __shfl_xor_sync(~0u, csum, o);
    if ((tid & 31) == 0) red[tid >> 5] = csum;
    __syncthreads();
    if (tid == 0) {
        float s = 0.f;
        for (int i = 0; i < 16; i++) s += red[i];
        atomicAdd(&g_csum, s);
    }
}

// ---------------- decoder (512 threads, consumes z_q_st) ----------------
#define DEC_SMEM ((8320+16384+4096+1024+16640+4352)*4)
#define DTH 512
__global__ __launch_bounds__(DTH, 1) void k_decoder(
    const float* __restrict__ x,
    const float* __restrict__ revin_w, const float* __restrict__ revin_b,
    const float* __restrict__ W1, const float* __restrict__ b1,
    const float* __restrict__ W2, const float* __restrict__ b2,
    const float* __restrict__ Wr, const float* __restrict__ br,
    const float* __restrict__ lg, const float* __restrict__ lb,
    float* __restrict__ out, int out_size)
{
    extern __shared__ float S[];
    float* zq  = S;                 // stride 65
    float* sW1 = S + 8320;
    float* sW2 = S + 24704;
    float* sWr = S + 28800;
    float* U   = S + 29824;         // 64 x 260
    float* Yq  = S + 46464;         // 64 x 68
    __shared__ float red[16];

    int n = blockIdx.x, tid = threadIdx.x;
    int b = n >> 5, c = n & 31;
    for (int i = tid; i < 8192; i += DTH)
        zq[(i >> 6) * 65 + (i & 63)] = g_zq[(size_t)n * 8192 + i];
    for (int i = tid; i < 16384; i += DTH) sW1[i] = W1[i];
    for (int i = tid; i < 4096; i += DTH) sW2[i] = W2[i];
    for (int i = tid; i < 1024; i += DTH) sWr[i] = Wr[i];
    __syncthreads();
    float rw = revin_w[c], rbv = revin_b[c];
    float mu = g_mean[n], sd = g_stdv[n];
    const float* xb = x + (size_t)b * LL * CC + c;
    float rsum = 0.f;

    const int tgf = tid >> 6;            // 0..7 -> 4 tokens each (of 32)
    const int hq4 = (tid & 63) * 4;
    const int jq2 = (tid & 7) * 2;       // 2 of 16 outputs
    const int tp  = tid >> 3;            // 0..63 -> 1 token (of 64)

    for (int half = 0; half < 2; half++) {
        int hb = half * 64;
        // W1 GEMM for the half's 64 tokens in two 32-token passes
        for (int ss = 0; ss < 2; ss++) {
            int tb = hb + ss * 32;
            float acc[4][4];
            float4 b4 = *(const float4*)&b1[hq4];
            #pragma unroll
            for (int j = 0; j < 4; j++) {
                acc[j][0] = b4.x; acc[j][1] = b4.y; acc[j][2] = b4.z; acc[j][3] = b4.w;
            }
            for (int e = 0; e < 64; e++) {
                float4 w4 = *(const float4*)&sW1[e * 256 + hq4];
                #pragma unroll
                for (int j = 0; j < 4; j++) {
                    float zv = zq[(tb + tgf * 4 + j) * 65 + e];
                    acc[j][0] = __fmaf_rn(zv, w4.x, acc[j][0]);
                    acc[j][1] = __fmaf_rn(zv, w4.y, acc[j][1]);
                    acc[j][2] = __fmaf_rn(zv, w4.z, acc[j][2]);
                    acc[j][3] = __fmaf_rn(zv, w4.w, acc[j][3]);
                }
            }
            #pragma unroll
            for (int j = 0; j < 4; j++) {
                float4 o4;
                o4.x = fmaxf(acc[j][0], 0.f); o4.y = fmaxf(acc[j][1], 0.f);
                o4.z = fmaxf(acc[j][2], 0.f); o4.w = fmaxf(acc[j][3], 0.f);
                *(float4*)&U[(ss * 32 + tgf * 4 + j) * 260 + hq4] = o4;
            }
        }
        __syncthreads();
        // W2 + Wr: 1tok x 2j tiles over 64 tokens
        {
            float a0 = b2[jq2]     + br[jq2];
            float a1 = b2[jq2 + 1] + br[jq2 + 1];
            for (int e2 = 0; e2 < 256; e2++) {
                float w0 = sW2[e2 * 16 + jq2], w1 = sW2[e2 * 16 + jq2 + 1];
                float uv = U[tp * 260 + e2];
                a0 = __fmaf_rn(uv, w0, a0);
                a1 = __fmaf_rn(uv, w1, a1);
            }
            for (int e = 0; e < 64; e++) {
                float w0 = sWr[e * 16 + jq2], w1 = sWr[e * 16 + jq2 + 1];
                float zv = zq[(hb + tp) * 65 + e];
                a0 = __fmaf_rn(zv, w0, a0);
                a1 = __fmaf_rn(zv, w1, a1);
            }
            Yq[tp * 68 + jq2]     = a0;
            Yq[tp * 68 + jq2 + 1] = a1;
        }
        __syncthreads();
        // LN + RevIN denorm + rec-loss for the half's 64 tokens
        if (tid < 64) {
            int tl = tid, p = hb + tl;
            float vals[16], s = 0.f;
            #pragma unroll
            for (int j = 0; j < 16; j++) { vals[j] = Yq[tl * 68 + j]; s += vals[j]; }
            float mn = s * (1.f / 16.f);
            float q = 0.f;
            #pragma unroll
            for (int j = 0; j < 16; j++) { float d = vals[j] - mn; q += d * d; }
            float r = rsqrtf(q * (1.f / 16.f) + 1e-5f);
            #pragma unroll
            for (int j = 0; j < 16; j++) {
                float rp = (vals[j] - mn) * r * lg[j] + lb[j];
                float rv = (rp - rbv) / (rw + 1e-10f) * sd + mu;
                int l = p * 16 + j;
                size_t oo = O_R + ((size_t)b * LL + l) * CC + c;
                if (oo < (size_t)out_size) out[oo] = rv;
                float xv = xb[(size_t)l * CC];
                float d = xv - rv;
                rsum += d * d;
            }
        }
        __syncthreads();
    }
    #pragma unroll
    for (int o = 16; o > 0; o >>= 1) rsum += __shfl_xor_sync(~0u, rsum, o);
    if ((tid & 31) == 0) red[tid >> 5] = rsum;
    __syncthreads();
    if (tid == 0) {
        float s = 0.f;
        for (int i = 0; i < 16; i++) s += red[i];
        atomicAdd(&g_rsum, s);
    }
}

// ---------------- finalize scalars ----------------
__global__ void k_final(float* __restrict__ out, int out_size) {
    __shared__ float sh[512];
    int tid = threadIdx.x;
    float cnt = g_counts[tid];
    sh[tid] = cnt; __syncthreads();
    for (int s = 256; s > 0; s >>= 1) { if (tid < s) sh[tid] += sh[tid + s]; __syncthreads(); }
    float total = sh[0];
    __syncthreads();
    float p = cnt / (total + 1e-5f);
    float ent = -p * logf(p + 1e-5f);
    sh[tid] = ent; __syncthreads();
    for (int s = 256; s > 0; s >>= 1) { if (tid < s) sh[tid] += sh[tid + s]; __syncthreads(); }
    if (tid == 0) {
        float perp = expf(sh[0]);
        float rec = g_rsum / (float)((size_t)BB * LL * CC);
        float cl = g_csum / (float)((size_t)NTOK * DD);
        float cluster = cl + 0.25f * cl;
        float lt = rec + 0.2f * cluster;
        if (out_size > 0) out[0] = lt;
        if (out_size > 1) out[1] = rec;
        if (O_PERP < (size_t)out_size) out[O_PERP] = perp;
    }
}

// ---------------- launch ----------------
extern "C" void kernel_launch(void* const* d_in, const int* in_sizes, int n_in,
                              void* d_out, int out_size) {
    const float* x       = (const float*)d_in[0];
    const float* revin_w = (const float*)d_in[1];
    const float* revin_b = (const float*)d_in[2];
    const float* inp_W   = (const float*)d_in[3];
    const float* inp_b   = (const float*)d_in[4];
    const float* Wq      = (const float*)d_in[5];
    const float* bq      = (const float*)d_in[6];
    const float* Wk      = (const float*)d_in[7];
    const float* bk      = (const float*)d_in[8];
    const float* Wv      = (const float*)d_in[9];
    const float* bv      = (const float*)d_in[10];
    const float* Wo      = (const float*)d_in[11];
    const float* bo      = (const float*)d_in[12];
    const float* ln1_g   = (const float*)d_in[13];
    const float* ln1_b   = (const float*)d_in[14];
    const float* fW1     = (const float*)d_in[15];
    const float* fb1     = (const float*)d_in[16];
    const float* fW2     = (const float*)d_in[17];
    const float* fb2     = (const float*)d_in[18];
    const float* ln2_g   = (const float*)d_in[19];
    const float* ln2_b   = (const float*)d_in[20];
    const float* codebook= (const float*)d_in[21];
    const float* dW1     = (const float*)d_in[22];
    const float* db1     = (const float*)d_in[23];
    const float* dW2     = (const float*)d_in[24];
    const float* db2     = (const float*)d_in[25];
    const float* dWr     = (const float*)d_in[26];
    const float* dbr     = (const float*)d_in[27];
    const float* dlg     = (const float*)d_in[28];
    const float* dlb     = (const float*)d_in[29];
    float* out = (float*)d_out;

    cudaFuncSetAttribute(k_encoder, cudaFuncAttributeMaxDynamicSharedMemorySize, ENC_SMEM);
    cudaFuncSetAttribute(k_quant,   cudaFuncAttributeMaxDynamicSharedMemorySize, QUANT_SMEM);
    cudaFuncSetAttribute(k_decoder, cudaFuncAttributeMaxDynamicSharedMemorySize, DEC_SMEM);

    k_init<<<1, 512>>>();
    k_revin<<<BB, 1024>>>(x);
    k_encoder<<<NSEQ, ETH, ENC_SMEM>>>(x, revin_w, revin_b, inp_W, inp_b,
                                       Wq, bq, Wk, bk, Wv, bv, Wo, bo,
                                       ln1_g, ln1_b, fW1, fb1, fW2, fb2, ln2_g, ln2_b);
    k_quant<<<NSEQ, QTH, QUANT_SMEM>>>(codebook, out, out_size);
    k_decoder<<<NSEQ, DTH, DEC_SMEM>>>(x, revin_w, revin_b, dW1, db1, dW2, db2,
                                       dWr, dbr, dlg, dlb, out, out_size);
    k_final<<<1, 512>>>(out, out_size);
}

// round 14
// speedup vs baseline: 1.1688x; 1.1688x over previous
#include <cuda_runtime.h>
#include <cuda_bf16.h>
#include <math.h>

// ---------------- problem constants ----------------
#define BB 32
#define LL 2048
#define CC 32
#define PLEN 16
#define PP 128
#define DD 64
#define HENC 256
#define HDEC 256
#define KK 512
#define NHEAD 4
#define DH 16
#define NSEQ 1024
#define NTOK (NSEQ*PP)

#define O_ZQ   ((size_t)2)
#define O_R    ((size_t)(2 + (size_t)NTOK*DD))
#define O_IDX  ((size_t)(O_R + (size_t)BB*LL*CC))
#define O_PERP ((size_t)(O_IDX + (size_t)NTOK))

// ---------------- packed f32x2 helpers (sm_103a FFMA2) ----------------
typedef unsigned long long u64;
__device__ __forceinline__ u64 pk2(float lo, float hi) {
    u64 r; asm("mov.b64 %0, {%1, %2};" : "=l"(r) : "f"(lo), "f"(hi)); return r;
}
__device__ __forceinline__ void fma2(u64& d, u64 a, u64 b) {
    asm("fma.rn.f32x2 %0, %1, %2, %0;" : "+l"(d) : "l"(a), "l"(b));
}
__device__ __forceinline__ float2 upk2(u64 v) {
    float2 r; asm("mov.b64 {%0, %1}, %2;" : "=f"(r.x), "=f"(r.y) : "l"(v)); return r;
}

// ---------------- device scratch ----------------
__device__ float g_mean[NSEQ];
__device__ float g_istd[NSEQ];
__device__ float g_stdv[NSEQ];
__device__ float g_z [(size_t)NTOK*DD];
__device__ float g_zq[(size_t)NTOK*DD];
__device__ float g_counts[KK];
__device__ float g_csum;
__device__ float g_rsum;

// ---------------- init ----------------
__global__ void k_init() {
    int t = threadIdx.x;
    if (t < KK) g_counts[t] = 0.f;
    if (t == 0) { g_csum = 0.f; g_rsum = 0.f; }
}

// ---------------- RevIN stats ----------------
__global__ void k_revin(const float* __restrict__ x) {
    __shared__ float ps[32][33], pq[32][33];
    int b = blockIdx.x;
    int c = threadIdx.x & 31, ls = threadIdx.x >> 5;
    const float* xb = x + (size_t)b * LL * CC;
    float s = 0.f, q = 0.f;
    for (int l = ls; l < LL; l += 32) {
        float v = xb[(size_t)l * CC + c];
        s += v; q += v * v;
    }
    ps[ls][c] = s; pq[ls][c] = q;
    __syncthreads();
    if (threadIdx.x < 32) {
        int cc = threadIdx.x;
        float S = 0.f, Q = 0.f;
        for (int i = 0; i < 32; i++) { S += ps[i][cc]; Q += pq[i][cc]; }
        float m = S / (float)LL;
        float var = Q / (float)LL - m * m;
        float sd = sqrtf(var + 1e-5f);
        g_mean[b * 32 + cc] = m;
        g_stdv[b * 32 + cc] = sd;
        g_istd[b * 32 + cc] = 1.f / sd;
    }
}

// ---------------- fused encoder (256 threads, R6 structure + f32x2) ----------------
#define ENC_SMEM 206336
__global__ __launch_bounds__(256, 1) void k_encoder(
    const float* __restrict__ x,
    const float* __restrict__ revin_w, const float* __restrict__ revin_b,
    const float* __restrict__ inp_W, const float* __restrict__ inp_b,
    const float* __restrict__ Wq, const float* __restrict__ bq,
    const float* __restrict__ Wk, const float* __restrict__ bk,
    const float* __restrict__ Wv, const float* __restrict__ bv,
    const float* __restrict__ Wo, const float* __restrict__ bo,
    const float* __restrict__ ln1_g, const float* __restrict__ ln1_b,
    const float* __restrict__ fW1, const float* __restrict__ fb1,
    const float* __restrict__ fW2, const float* __restrict__ fb2,
    const float* __restrict__ ln2_g, const float* __restrict__ ln2_b)
{
    extern __shared__ float S[];
    float* h  = S;
    float* A  = S + 8320;
    float* Bb = S + 16640;
    float* Cc = S + 24960;
    float* wb = S + 33280;
    const int tid = threadIdx.x;
    const int n = blockIdx.x;
    const int b = n >> 5, c = n & 31;
    const float mu = g_mean[n], is = g_istd[n];
    const float rw = revin_w[c], rb = revin_b[c];
    const float* xb = x + (size_t)b * LL * CC + c;

    // P0
    for (int i = tid; i < 2048; i += 256)
        A[i] = (xb[(size_t)i * CC] - mu) * is * rw + rb;
    for (int i = tid; i < 1024 + 64; i += 256)
        wb[i] = (i < 1024) ? inp_W[i] : inp_b[i - 1024];
    __syncthreads();

    // P1: h = xn @ inp_W + b (small; scalar)
    for (int i = tid; i < 8192; i += 256) {
        int p = i >> 6, d = i & 63;
        float acc = wb[1024 + d];
        const float* xn = A + p * 16;
        #pragma unroll
        for (int j = 0; j < 16; j++) acc = __fmaf_rn(xn[j], wb[j * 64 + d], acc);
        h[p * 65 + d] = acc;
    }

    // P2: q,k,v — 8tok x 2 d-pairs, FFMA2
    {
        const float* Ws[3] = {Wq, Wk, Wv};
        const float* bs[3] = {bq, bk, bv};
        float* dsts[3] = {A, Bb, Cc};
        const int tg8 = tid >> 4;
        const int dq4 = (tid & 15) * 4;
        for (int m = 0; m < 3; m++) {
            __syncthreads();
            const float* W = Ws[m]; const float* bi = bs[m];
            for (int i = tid; i < 4160; i += 256)
                wb[i] = (i < 4096) ? W[i] : bi[i - 4096];
            __syncthreads();
            u64 acc[8][2];
            {
                ulonglong2 bb = *(const ulonglong2*)&wb[4096 + dq4];
                #pragma unroll
                for (int j = 0; j < 8; j++) { acc[j][0] = bb.x; acc[j][1] = bb.y; }
            }
            for (int e = 0; e < 64; e++) {
                ulonglong2 wp = *(const ulonglong2*)&wb[e * 64 + dq4];
                #pragma unroll
                for (int j = 0; j < 8; j++) {
                    float hv = h[(tg8 * 8 + j) * 65 + e];
                    u64 hb2 = pk2(hv, hv);
                    fma2(acc[j][0], wp.x, hb2);
                    fma2(acc[j][1], wp.y, hb2);
                }
            }
            float* dst = dsts[m];
            #pragma unroll
            for (int j = 0; j < 8; j++) {
                int row = (tg8 * 8 + j) * 65 + dq4;
                float2 lo = upk2(acc[j][0]), hi = upk2(acc[j][1]);
                dst[row + 0] = lo.x; dst[row + 1] = lo.y;
                dst[row + 2] = hi.x; dst[row + 3] = hi.y;
            }
        }
    }
    __syncthreads();

    // P3: attention — 512 rows, 2/thread, online softmax (scalar, order-critical)
    for (int rr = 0; rr < 2; rr++) {
        int row = tid + rr * 256;
        int hh = row >> 7, qq = row & 127;
        int off = hh * 16;
        float qv[16], acc[16];
        #pragma unroll
        for (int t = 0; t < 16; t++) { qv[t] = A[qq * 65 + off + t]; acc[t] = 0.f; }
        float mx = -1e30f, l = 0.f;
        for (int j = 0; j < 128; j++) {
            const float* kj = Bb + j * 65 + off;
            float s = 0.f;
            #pragma unroll
            for (int t = 0; t < 16; t++) s += qv[t] * kj[t];
            s *= 0.25f;
            float nm = fmaxf(mx, s);
            float corr = __expf(mx - nm);
            float pw = __expf(s - nm);
            l = l * corr + pw;
            const float* vj = Cc + j * 65 + off;
            #pragma unroll
            for (int t = 0; t < 16; t++) acc[t] = acc[t] * corr + pw * vj[t];
            mx = nm;
        }
        float il = 1.f / l;
        #pragma unroll
        for (int t = 0; t < 16; t++) A[qq * 65 + off + t] = acc[t] * il;
    }
    __syncthreads();

    // P4: o = a @ Wo + bo + h -> Bb; FFMA2; then LN1 -> h
    for (int i = tid; i < 4160; i += 256)
        wb[i] = (i < 4096) ? Wo[i] : bo[i - 4096];
    __syncthreads();
    {
        const int tg8 = tid >> 4;
        const int dq4 = (tid & 15) * 4;
        u64 acc[8][2];
        {
            float4 b4 = *(const float4*)&wb[4096 + dq4];
            #pragma unroll
            for (int j = 0; j < 8; j++) {
                int row = (tg8 * 8 + j) * 65 + dq4;
                acc[j][0] = pk2(b4.x + h[row + 0], b4.y + h[row + 1]);
                acc[j][1] = pk2(b4.z + h[row + 2], b4.w + h[row + 3]);
            }
        }
        for (int e = 0; e < 64; e++) {
            ulonglong2 wp = *(const ulonglong2*)&wb[e * 64 + dq4];
            #pragma unroll
            for (int j = 0; j < 8; j++) {
                float av = A[(tg8 * 8 + j) * 65 + e];
                u64 ab2 = pk2(av, av);
                fma2(acc[j][0], wp.x, ab2);
                fma2(acc[j][1], wp.y, ab2);
            }
        }
        #pragma unroll
        for (int j = 0; j < 8; j++) {
            int row = (tg8 * 8 + j) * 65 + dq4;
            float2 lo = upk2(acc[j][0]), hi = upk2(acc[j][1]);
            Bb[row + 0] = lo.x; Bb[row + 1] = lo.y;
            Bb[row + 2] = hi.x; Bb[row + 3] = hi.y;
        }
    }
    __syncthreads();
    // LN1
    {
        int w = tid >> 5, lane = tid & 31;
        for (int p = w; p < 128; p += 8) {
            float v0 = Bb[p * 65 + lane], v1 = Bb[p * 65 + lane + 32];
            float s = v0 + v1;
            #pragma unroll
            for (int o = 16; o > 0; o >>= 1) s += __shfl_xor_sync(~0u, s, o);
            float mean = s * (1.f / 64.f);
            float d0 = v0 - mean, d1 = v1 - mean;
            float q = d0 * d0 + d1 * d1;
            #pragma unroll
            for (int o = 16; o > 0; o >>= 1) q += __shfl_xor_sync(~0u, q, o);
            float r = rsqrtf(q * (1.f / 64.f) + 1e-5f);
            h[p * 65 + lane]      = d0 * r * ln1_g[lane]      + ln1_b[lane];
            h[p * 65 + lane + 32] = d1 * r * ln1_g[lane + 32] + ln1_b[lane + 32];
        }
    }
    __syncthreads();

    // P5: FFN in four 32-token quarters; FFMA2
    float* WB1 = S + 8320;
    float* WB2 = S + 24704;
    float* U   = S + 41088;   // 32 x 260
    float* Yq  = S + 49408;   // 32 x 68
    for (int i = tid; i < 16384; i += 256) WB1[i] = fW1[i];
    for (int i = tid; i < 16384; i += 256) WB2[i] = fW2[i];
    __syncthreads();
    const int tgf = tid >> 6;            // 0..3 -> 8 tokens
    const int hq4 = (tid & 63) * 4;
    const int tg2 = tid >> 4;            // 0..15 -> 2 tokens
    const int dq4 = (tid & 15) * 4;
    for (int qtr = 0; qtr < 4; qtr++) {
        int tb = qtr * 32;
        // FFN1: u = relu(h @ W1 + b1)
        {
            u64 acc[8][2];
            float4 b4 = *(const float4*)&fb1[hq4];
            u64 bb0 = pk2(b4.x, b4.y), bb1 = pk2(b4.z, b4.w);
            #pragma unroll
            for (int j = 0; j < 8; j++) { acc[j][0] = bb0; acc[j][1] = bb1; }
            for (int e = 0; e < 64; e++) {
                ulonglong2 wp = *(const ulonglong2*)&WB1[e * 256 + hq4];
                #pragma unroll
                for (int j = 0; j < 8; j++) {
                    float hv = h[(tb + tgf * 8 + j) * 65 + e];
                    u64 hb2 = pk2(hv, hv);
                    fma2(acc[j][0], wp.x, hb2);
                    fma2(acc[j][1], wp.y, hb2);
                }
            }
            #pragma unroll
            for (int j = 0; j < 8; j++) {
                float2 lo = upk2(acc[j][0]), hi = upk2(acc[j][1]);
                float4 o4;
                o4.x = fmaxf(lo.x, 0.f); o4.y = fmaxf(lo.y, 0.f);
                o4.z = fmaxf(hi.x, 0.f); o4.w = fmaxf(hi.y, 0.f);
                *(float4*)&U[(tgf * 8 + j) * 260 + hq4] = o4;
            }
        }
        __syncthreads();
        // FFN2: o = u @ W2 + b2 + h
        {
            u64 acc[2][2];
            #pragma unroll
            for (int jj = 0; jj < 2; jj++) {
                int tok = tb + tg2 * 2 + jj;
                acc[jj][0] = pk2(fb2[dq4 + 0] + h[tok * 65 + dq4 + 0],
                                 fb2[dq4 + 1] + h[tok * 65 + dq4 + 1]);
                acc[jj][1] = pk2(fb2[dq4 + 2] + h[tok * 65 + dq4 + 2],
                                 fb2[dq4 + 3] + h[tok * 65 + dq4 + 3]);
            }
            for (int e2 = 0; e2 < 256; e2++) {
                ulonglong2 wp = *(const ulonglong2*)&WB2[e2 * 64 + dq4];
                #pragma unroll
                for (int jj = 0; jj < 2; jj++) {
                    float uv = U[(tg2 * 2 + jj) * 260 + e2];
                    u64 up = pk2(uv, uv);
                    fma2(acc[jj][0], wp.x, up);
                    fma2(acc[jj][1], wp.y, up);
                }
            }
            #pragma unroll
            for (int jj = 0; jj < 2; jj++) {
                int tl = tg2 * 2 + jj;
                float2 lo = upk2(acc[jj][0]), hi = upk2(acc[jj][1]);
                float4 o4; o4.x = lo.x; o4.y = lo.y; o4.z = hi.x; o4.w = hi.y;
                *(float4*)&Yq[tl * 68 + dq4] = o4;
            }
        }
        __syncthreads();
        // LN2 -> h
        {
            int w = tid >> 5, lane = tid & 31;
            for (int tl = w; tl < 32; tl += 8) {
                float v0 = Yq[tl * 68 + lane], v1 = Yq[tl * 68 + lane + 32];
                float s = v0 + v1;
                #pragma unroll
                for (int o = 16; o > 0; o >>= 1) s += __shfl_xor_sync(~0u, s, o);
                float mean = s * (1.f / 64.f);
                float d0 = v0 - mean, d1 = v1 - mean;
                float q = d0 * d0 + d1 * d1;
                #pragma unroll
                for (int o = 16; o > 0; o >>= 1) q += __shfl_xor_sync(~0u, q, o);
                float r = rsqrtf(q * (1.f / 64.f) + 1e-5f);
                h[(tb + tl) * 65 + lane]      = d0 * r * ln2_g[lane]      + ln2_b[lane];
                h[(tb + tl) * 65 + lane + 32] = d1 * r * ln2_g[lane + 32] + ln2_b[lane + 32];
            }
        }
        __syncthreads();
    }
    float* zo = g_z + (size_t)n * 8192;
    for (int i = tid; i < 8192; i += 256) zo[i] = h[(i >> 6) * 65 + (i & 63)];
}

// ---------------- quantizer (256 threads, FFMA2 on code pairs) ----------------
#define QUANT_SMEM ((8448+8448+128+128+1024+1024)*4)
__global__ __launch_bounds__(256, 1) void k_quant(
    const float* __restrict__ cb, float* __restrict__ out, int out_size)
{
    extern __shared__ float S[];
    float* zT   = S;
    float* cbsT = S + 8448;
    float* e2s  = S + 16896;
    float* z2s  = S + 17024;
    float* bd   = S + 17152;
    int*   bki  = (int*)(S + 18176);
    __shared__ float red[8];

    int n = blockIdx.x, tid = threadIdx.x;
    const float* z = g_z + (size_t)n * 8192;
    for (int i = tid; i < 8192; i += 256) {
        int tok = i >> 6, e = i & 63;
        zT[e * 132 + tok] = z[i];
    }
    __syncthreads();
    if (tid < 128) {
        float acc = 0.f;
        #pragma unroll 8
        for (int e = 0; e < 64; e++) {
            float v = zT[e * 132 + tid];
            acc = __fmaf_rn(v, v, acc);
        }
        z2s[tid] = acc;
    }

    const int tg   = tid & 31;
    const int crow = tid >> 5;
    const int tok0 = tg * 4;
    float bestd[4]; int bestk[4];
    #pragma unroll
    for (int t = 0; t < 4; t++) { bestd[t] = 1e30f; bestk[t] = 0; }

    for (int ch = 0; ch < 4; ch++) {
        __syncthreads();
        for (int i = tid; i < 8192; i += 256) {
            int cl = i >> 6, e = i & 63;
            cbsT[e * 132 + cl] = cb[ch * 8192 + i];
        }
        __syncthreads();
        if (tid < 128) {
            float s = 0.f;
            #pragma unroll 8
            for (int e = 0; e < 64; e++) {
                float v = cbsT[e * 132 + tid];
                s = __fmaf_rn(v, v, s);
            }
            e2s[tid] = s;
        }
        __syncthreads();
        #pragma unroll
        for (int sub = 0; sub < 2; sub++) {
            int cbase = sub * 64 + crow * 8;
            // acc[t][p] = packed dot pair for codes (cbase+2p, cbase+2p+1)
            u64 acc[4][4];
            #pragma unroll
            for (int t = 0; t < 4; t++)
                #pragma unroll
                for (int p = 0; p < 4; p++) acc[t][p] = 0ULL;
            for (int e = 0; e < 64; e++) {
                float4 zv = *(const float4*)&zT[e * 132 + tok0];
                ulonglong2 cp0 = *(const ulonglong2*)&cbsT[e * 132 + cbase];
                ulonglong2 cp1 = *(const ulonglong2*)&cbsT[e * 132 + cbase + 4];
                u64 zb[4] = {pk2(zv.x, zv.x), pk2(zv.y, zv.y),
                             pk2(zv.z, zv.z), pk2(zv.w, zv.w)};
                #pragma unroll
                for (int t = 0; t < 4; t++) {
                    fma2(acc[t][0], cp0.x, zb[t]);
                    fma2(acc[t][1], cp0.y, zb[t]);
                    fma2(acc[t][2], cp1.x, zb[t]);
                    fma2(acc[t][3], cp1.y, zb[t]);
                }
            }
            #pragma unroll
            for (int p = 0; p < 4; p++) {
                float2 dots[4];
                #pragma unroll
                for (int t = 0; t < 4; t++) dots[t] = upk2(acc[t][p]);
                #pragma unroll
                for (int hf = 0; hf < 2; hf++) {
                    int kl = cbase + p * 2 + hf;
                    int kg = ch * 128 + kl;
                    float e2v = e2s[kl];
                    #pragma unroll
                    for (int t = 0; t < 4; t++) {
                        float dot = hf ? dots[t].y : dots[t].x;
                        float dist = __fsub_rn(__fadd_rn(z2s[tok0 + t], e2v),
                                               __fmul_rn(2.0f, dot));
                        if (dist < bestd[t]) { bestd[t] = dist; bestk[t] = kg; }
                    }
                }
            }
        }
    }
    #pragma unroll
    for (int t = 0; t < 4; t++) {
        bd[crow * 128 + tok0 + t] = bestd[t];
        bki[crow * 128 + tok0 + t] = bestk[t];
    }
    __syncthreads();
    if (tid < 128) {
        float d0 = bd[tid]; int k0 = bki[tid];
        #pragma unroll
        for (int r = 1; r < 8; r++) {
            float d1 = bd[r * 128 + tid]; int k1 = bki[r * 128 + tid];
            if (d1 < d0 || (d1 == d0 && k1 < k0)) { d0 = d1; k0 = k1; }
        }
        bki[tid] = k0;
        atomicAdd(&g_counts[k0], 1.f);
        size_t oi = O_IDX + (size_t)n * 128 + tid;
        if (oi < (size_t)out_size) out[oi] = (float)k0;
    }
    __syncthreads();
    float csum = 0.f;
    float* zq = g_zq + (size_t)n * 8192;
    for (int i = tid; i < 8192; i += 256) {
        int t2 = i >> 6, e = i & 63;
        int kf = bki[t2];
        float q = cb[kf * 64 + e];
        float zz = z[i];
        float d = __fsub_rn(q, zz);
        csum += d * d;
        float q_st = __fadd_rn(zz, d);
        zq[i] = q_st;
        size_t oo = O_ZQ + (size_t)n * 8192 + i;
        if (oo < (size_t)out_size) out[oo] = q_st;
    }
    #pragma unroll
    for (int o = 16; o > 0; o >>= 1) csum += __shfl_xor_sync(~0u, csum, o);
    if ((tid & 31) == 0) red[tid >> 5] = csum;
    __syncthreads();
    if (tid == 0) {
        float s = 0.f;
        for (int i = 0; i < 8; i++) s += red[i];
        atomicAdd(&g_csum, s);
    }
}

// ---------------- decoder (256 threads, FFMA2) ----------------
#define DEC_SMEM ((8320+16384+4096+1024+16640+4352)*4)
__global__ __launch_bounds__(256, 1) void k_decoder(
    const float* __restrict__ x,
    const float* __restrict__ revin_w, const float* __restrict__ revin_b,
    const float* __restrict__ W1, const float* __restrict__ b1,
    const float* __restrict__ W2, const float* __restrict__ b2,
    const float* __restrict__ Wr, const float* __restrict__ br,
    const float* __restrict__ lg, const float* __restrict__ lb,
    float* __restrict__ out, int out_size)
{
    extern __shared__ float S[];
    float* zq  = S;                 // stride 65
    float* sW1 = S + 8320;
    float* sW2 = S + 24704;
    float* sWr = S + 28800;
    float* U   = S + 29824;         // 64 x 260
    float* Yq  = S + 46464;         // 64 x 68
    __shared__ float red[8];

    int n = blockIdx.x, tid = threadIdx.x;
    int b = n >> 5, c = n & 31;
    for (int i = tid; i < 8192; i += 256)
        zq[(i >> 6) * 65 + (i & 63)] = g_zq[(size_t)n * 8192 + i];
    for (int i = tid; i < 16384; i += 256) sW1[i] = W1[i];
    for (int i = tid; i < 4096; i += 256) sW2[i] = W2[i];
    for (int i = tid; i < 1024; i += 256) sWr[i] = Wr[i];
    __syncthreads();
    float rw = revin_w[c], rbv = revin_b[c];
    float mu = g_mean[n], sd = g_stdv[n];
    const float* xb = x + (size_t)b * LL * CC + c;
    float rsum = 0.f;

    const int tgf = tid >> 6;
    const int hq4 = (tid & 63) * 4;
    const int jq2 = (tid & 7) * 2;
    const int tp  = tid >> 3;        // 0..31 -> 2 tokens

    for (int half = 0; half < 2; half++) {
        int hb = half * 64;
        // W1 GEMM in two 32-token passes
        for (int ss = 0; ss < 2; ss++) {
            int tb = hb + ss * 32;
            u64 acc[8][2];
            float4 b4 = *(const float4*)&b1[hq4];
            u64 bb0 = pk2(b4.x, b4.y), bb1 = pk2(b4.z, b4.w);
            #pragma unroll
            for (int j = 0; j < 8; j++) { acc[j][0] = bb0; acc[j][1] = bb1; }
            for (int e = 0; e < 64; e++) {
                ulonglong2 wp = *(const ulonglong2*)&sW1[e * 256 + hq4];
                #pragma unroll
                for (int j = 0; j < 8; j++) {
                    float zv = zq[(tb + tgf * 8 + j) * 65 + e];
                    u64 zb2 = pk2(zv, zv);
                    fma2(acc[j][0], wp.x, zb2);
                    fma2(acc[j][1], wp.y, zb2);
                }
            }
            #pragma unroll
            for (int j = 0; j < 8; j++) {
                float2 lo = upk2(acc[j][0]), hi = upk2(acc[j][1]);
                float4 o4;
                o4.x = fmaxf(lo.x, 0.f); o4.y = fmaxf(lo.y, 0.f);
                o4.z = fmaxf(hi.x, 0.f); o4.w = fmaxf(hi.y, 0.f);
                *(float4*)&U[(ss * 32 + tgf * 8 + j) * 260 + hq4] = o4;
            }
        }
        __syncthreads();
        // W2 + Wr: 2tok x 1 j-pair
        {
            float a0i = b2[jq2]     + br[jq2];
            float a1i = b2[jq2 + 1] + br[jq2 + 1];
            u64 accp[2] = {pk2(a0i, a1i), pk2(a0i, a1i)};
            for (int e2 = 0; e2 < 256; e2++) {
                u64 wp = *(const u64*)&sW2[e2 * 16 + jq2];
                #pragma unroll
                for (int jj = 0; jj < 2; jj++) {
                    float uv = U[(tp * 2 + jj) * 260 + e2];
                    fma2(accp[jj], wp, pk2(uv, uv));
                }
            }
            for (int e = 0; e < 64; e++) {
                u64 wrp = *(const u64*)&sWr[e * 16 + jq2];
                #pragma unroll
                for (int jj = 0; jj < 2; jj++) {
                    float zv = zq[(hb + tp * 2 + jj) * 65 + e];
                    fma2(accp[jj], wrp, pk2(zv, zv));
                }
            }
            #pragma unroll
            for (int jj = 0; jj < 2; jj++) {
                int tl = tp * 2 + jj;
                float2 r2 = upk2(accp[jj]);
                Yq[tl * 68 + jq2]     = r2.x;
                Yq[tl * 68 + jq2 + 1] = r2.y;
            }
        }
        __syncthreads();
        // LN + RevIN denorm + rec-loss
        if (tid < 64) {
            int tl = tid, p = hb + tl;
            float vals[16], s = 0.f;
            #pragma unroll
            for (int j = 0; j < 16; j++) { vals[j] = Yq[tl * 68 + j]; s += vals[j]; }
            float mn = s * (1.f / 16.f);
            float q = 0.f;
            #pragma unroll
            for (int j = 0; j < 16; j++) { float d = vals[j] - mn; q += d * d; }
            float r = rsqrtf(q * (1.f / 16.f) + 1e-5f);
            #pragma unroll
            for (int j = 0; j < 16; j++) {
                float rp = (vals[j] - mn) * r * lg[j] + lb[j];
                float rv = (rp - rbv) / (rw + 1e-10f) * sd + mu;
                int l = p * 16 + j;
                size_t oo = O_R + ((size_t)b * LL + l) * CC + c;
                if (oo < (size_t)out_size) out[oo] = rv;
                float xv = xb[(size_t)l * CC];
                float d = xv - rv;
                rsum += d * d;
            }
        }
        __syncthreads();
    }
    #pragma unroll
    for (int o = 16; o > 0; o >>= 1) rsum += __shfl_xor_sync(~0u, rsum, o);
    if ((tid & 31) == 0) red[tid >> 5] = rsum;
    __syncthreads();
    if (tid == 0) {
        float s = 0.f;
        for (int i = 0; i < 8; i++) s += red[i];
        atomicAdd(&g_rsum, s);
    }
}

// ---------------- finalize scalars ----------------
__global__ void k_final(float* __restrict__ out, int out_size) {
    __shared__ float sh[512];
    int tid = threadIdx.x;
    float cnt = g_counts[tid];
    sh[tid] = cnt; __syncthreads();
    for (int s = 256; s > 0; s >>= 1) { if (tid < s) sh[tid] += sh[tid + s]; __syncthreads(); }
    float total = sh[0];
    __syncthreads();
    float p = cnt / (total + 1e-5f);
    float ent = -p * logf(p + 1e-5f);
    sh[tid] = ent; __syncthreads();
    for (int s = 256; s > 0; s >>= 1) { if (tid < s) sh[tid] += sh[tid + s]; __syncthreads(); }
    if (tid == 0) {
        float perp = expf(sh[0]);
        float rec = g_rsum / (float)((size_t)BB * LL * CC);
        float cl = g_csum / (float)((size_t)NTOK * DD);
        float cluster = cl + 0.25f * cl;
        float lt = rec + 0.2f * cluster;
        if (out_size > 0) out[0] = lt;
        if (out_size > 1) out[1] = rec;
        if (O_PERP < (size_t)out_size) out[O_PERP] = perp;
    }
}

// ---------------- launch ----------------
extern "C" void kernel_launch(void* const* d_in, const int* in_sizes, int n_in,
                              void* d_out, int out_size) {
    const float* x       = (const float*)d_in[0];
    const float* revin_w = (const float*)d_in[1];
    const float* revin_b = (const float*)d_in[2];
    const float* inp_W   = (const float*)d_in[3];
    const float* inp_b   = (const float*)d_in[4];
    const float* Wq      = (const float*)d_in[5];
    const float* bq      = (const float*)d_in[6];
    const float* Wk      = (const float*)d_in[7];
    const float* bk      = (const float*)d_in[8];
    const float* Wv      = (const float*)d_in[9];
    const float* bv      = (const float*)d_in[10];
    const float* Wo      = (const float*)d_in[11];
    const float* bo      = (const float*)d_in[12];
    const float* ln1_g   = (const float*)d_in[13];
    const float* ln1_b   = (const float*)d_in[14];
    const float* fW1     = (const float*)d_in[15];
    const float* fb1     = (const float*)d_in[16];
    const float* fW2     = (const float*)d_in[17];
    const float* fb2     = (const float*)d_in[18];
    const float* ln2_g   = (const float*)d_in[19];
    const float* ln2_b   = (const float*)d_in[20];
    const float* codebook= (const float*)d_in[21];
    const float* dW1     = (const float*)d_in[22];
    const float* db1     = (const float*)d_in[23];
    const float* dW2     = (const float*)d_in[24];
    const float* db2     = (const float*)d_in[25];
    const float* dWr     = (const float*)d_in[26];
    const float* dbr     = (const float*)d_in[27];
    const float* dlg     = (const float*)d_in[28];
    const float* dlb     = (const float*)d_in[29];
    float* out = (float*)d_out;

    cudaFuncSetAttribute(k_encoder, cudaFuncAttributeMaxDynamicSharedMemorySize, ENC_SMEM);
    cudaFuncSetAttribute(k_quant,   cudaFuncAttributeMaxDynamicSharedMemorySize, QUANT_SMEM);
    cudaFuncSetAttribute(k_decoder, cudaFuncAttributeMaxDynamicSharedMemorySize, DEC_SMEM);

    k_init<<<1, 512>>>();
    k_revin<<<BB, 1024>>>(x);
    k_encoder<<<NSEQ, 256, ENC_SMEM>>>(x, revin_w, revin_b, inp_W, inp_b,
                                       Wq, bq, Wk, bk, Wv, bv, Wo, bo,
                                       ln1_g, ln1_b, fW1, fb1, fW2, fb2, ln2_g, ln2_b);
    k_quant<<<NSEQ, 256, QUANT_SMEM>>>(codebook, out, out_size);
    k_decoder<<<NSEQ, 256, DEC_SMEM>>>(x, revin_w, revin_b, dW1, db1, dW2, db2,
                                       dWr, dbr, dlg, dlb, out, out_size);
    k_final<<<1, 512>>>(out, out_size);
}